// round 11
// baseline (speedup 1.0000x reference)
#include <cuda_runtime.h>

// Problem constants
#define TD     64
#define MODES  16
#define MRI    32          // 2*MODES
#define PD     16384       // N*D pixels
#define SCOL   1048576     // PD*64 floats per time row
#define TILE_P 16
#define NBLK   (PD / TILE_P)   // 1024 CTAs
#define NTHR   256

typedef unsigned long long u64;

// Gauss-packed weights: g_W2[m][kind][c4][o], kind 0=WR,1=WI,2=WS(=WR+WI)
// entry = ( pack(W[4c4],W[4c4+1]), pack(W[4c4+2],W[4c4+3]) )
__device__ ulonglong2 g_W2[MODES * 3 * 16 * 64];   // 768 KB

// ---------- compile-time DFT coefficients ----------
__host__ __device__ constexpr float cos64(int k) {
    constexpr float COSQ[17] = {
        1.0f,
        0.995184726672197f, 0.980785280403230f, 0.956940335732209f,
        0.923879532511287f, 0.881921264348355f, 0.831469612302545f,
        0.773010453362737f, 0.707106781186548f, 0.634393284163645f,
        0.555570233019602f, 0.471396736825998f, 0.382683432365090f,
        0.290284677254462f, 0.195090322016128f, 0.098017140329561f,
        0.0f
    };
    k &= 63;
    float s = 1.0f;
    if (k > 32) k = 64 - k;
    if (k > 16) { k = 32 - k; s = -1.0f; }
    return s * COSQ[k];
}
__host__ __device__ constexpr float alpha64(int m) {
    return ((m == 0) ? 1.0f : 2.0f) / 64.0f;
}

// ---------- packed f32x2 helpers ----------
__device__ __forceinline__ u64 pack2(float a, float b) {
    u64 r;
    asm("mov.b64 %0, {%1, %2};" : "=l"(r) : "f"(a), "f"(b));
    return r;
}
__device__ __forceinline__ void unpack2(u64 v, float &lo, float &hi) {
    asm("mov.b64 {%0, %1}, %2;" : "=f"(lo), "=f"(hi) : "l"(v));
}
__device__ __forceinline__ void fma2(u64 &d, u64 a, u64 b) {
    asm("fma.rn.f32x2 %0, %1, %2, %0;" : "+l"(d) : "l"(a), "l"(b));
}
__device__ __forceinline__ u64 add2(u64 a, u64 b) {
    u64 r;
    asm("add.rn.f32x2 %0, %1, %2;" : "=l"(r) : "l"(a), "l"(b));
    return r;
}
__device__ __forceinline__ float hadd(u64 v) {
    float lo, hi;
    unpack2(v, lo, hi);
    return lo + hi;
}

// =====================================================================
// One-time weight repack: w[c][o][m][2] -> g_W2[m][kind][c4][o]
// kind: 0 = WR, 1 = WI, 2 = WR+WI
// =====================================================================
__global__ void __launch_bounds__(256) w_pack(const float* __restrict__ w) {
    int idx = blockIdx.x * 256 + threadIdx.x;     // 0 .. 49151
    if (idx >= MODES * 3 * 16 * 64) return;
    int m    = idx / 3072;
    int r    = idx % 3072;
    int kind = r >> 10;
    int c4   = (r >> 6) & 15;
    int o    = r & 63;

    float v[4];
#pragma unroll
    for (int j = 0; j < 4; j++) {
        int c = 4 * c4 + j;
        const float* b = w + ((((long)c * 64 + o) * MODES + m) << 1);
        float wr = b[0], wi = b[1];
        v[j] = (kind == 0) ? wr : (kind == 1) ? wi : (wr + wi);
    }
    ulonglong2 e;
    e.x = pack2(v[0], v[1]);
    e.y = pack2(v[2], v[3]);
    g_W2[idx] = e;
}

// =====================================================================
// Fused spectral conv. 256 threads, 16 pixels per CTA, 180 KB smem.
// smem layout (bytes):
//   [0      ,131072 ) XY  [mri][16p][64c] f32 — X, overwritten in-place
//                     per mode by Y (mode m owns rows 2m,2m+1)
//   [131072 ,180224 ) W planes (single-buffered, 48 KB):
//                     WR2 @ +0, WI2 @ +16K, WS2 @ +32K ; [c4][o] ulonglong2
//   [180224 ,184320 ) XS  [16p][32cp] u64 (4 KB) — XR+XI for current mode
// Stage 2 uses Gauss 3-multiply on 128 threads, 8 px/thread.
// =====================================================================
__global__ void __launch_bounds__(NTHR, 1) fused_spectral(const float* __restrict__ x,
                                                          float* __restrict__ out) {
    extern __shared__ __align__(16) char smem[];
    u64*        XY64 = reinterpret_cast<u64*>(smem);
    float*      XYf  = reinterpret_cast<float*>(smem);
    ulonglong2* Wall = reinterpret_cast<ulonglong2*>(smem + 131072);  // 3072 entries
    ulonglong2* WR2  = Wall;
    ulonglong2* WI2  = Wall + 1024;
    ulonglong2* WS2  = Wall + 2048;
    u64*        XSsm = reinterpret_cast<u64*>(smem + 180224);         // 512 entries

    const int tid = threadIdx.x;
    const int p0  = blockIdx.x * TILE_P;

    // ---- prefetch W for mode 0 (overlaps with stage 1 gmem reads) ----
    ulonglong2 wreg[12];
#pragma unroll
    for (int k = 0; k < 12; k++) wreg[k] = g_W2[tid + k * NTHR];

    // =============== Stage 1: truncated rfft into smem (folded) ===============
    {
        const int cp = tid & 31;
        const int pp = tid >> 5;           // 0..7, warp-uniform

        for (int pass = 0; pass < 2; pass++) {
            const int p = pp + pass * 8;
            const u64* xp = reinterpret_cast<const u64*>(x) + (long)(p0 + p) * 32 + cp;

            float XcL[16], XcH[16], XsL[16], XsH[16];
            {
                float x0L, x0H, x32L, x32H;
                unpack2(xp[0], x0L, x0H);
                unpack2(xp[32 * (SCOL / 2)], x32L, x32H);
#pragma unroll
                for (int m = 0; m < 16; m++) {
                    if (m & 1) { XcL[m] = x0L - x32L; XcH[m] = x0H - x32H; }
                    else       { XcL[m] = x0L + x32L; XcH[m] = x0H + x32H; }
                    XsL[m] = 0.0f; XsH[m] = 0.0f;
                }
            }

#pragma unroll
            for (int t = 1; t < 32; t++) {
                float aL, aH, bL, bH;
                unpack2(xp[(long)t * (SCOL / 2)], aL, aH);
                unpack2(xp[(long)(64 - t) * (SCOL / 2)], bL, bH);
                const float eL = aL + bL, eH = aH + bH;
                const float oL = aL - bL, oH = aH - bH;
                XcL[0] += eL; XcH[0] += eH;
#pragma unroll
                for (int m = 1; m < 16; m++) {
                    const float fc = cos64(m * t);
                    const float fs = cos64(m * t + 16);
                    if (fc != 0.0f) {
                        XcL[m] = fmaf(eL, fc, XcL[m]);
                        XcH[m] = fmaf(eH, fc, XcH[m]);
                    }
                    if (fs != 0.0f) {
                        XsL[m] = fmaf(oL, fs, XsL[m]);
                        XsH[m] = fmaf(oH, fs, XsH[m]);
                    }
                }
            }

#pragma unroll
            for (int m = 0; m < 16; m++) {
                XY64[((2 * m)     * TILE_P + p) * 32 + cp] = pack2(XcL[m], XcH[m]);
                XY64[((2 * m + 1) * TILE_P + p) * 32 + cp] = pack2(XsL[m], XsH[m]);
            }
        }
        // published at the first syncthreads inside the mode loop
    }

    // =============== Stage 2: per-mode Gauss complex channel mix ===============
    // 128 compute threads: o = tid&63, pixel-group = (tid>>6)*8; 8 px/thread.
    // All 256 threads stage W (12 STS.128) and XS (2 entries) per mode.
    {
        const int o  = tid & 63;
        const int pg = (tid >> 6) * 8;            // 0 or 8 for tid<128
        const bool active = (tid < 128);

        for (int m = 0; m < MODES; m++) {
            // store W_m plane set (prefetched earlier)
#pragma unroll
            for (int k = 0; k < 12; k++) Wall[tid + k * NTHR] = wreg[k];

            // XS = XR + XI for mode m. Each thread combines exactly the two
            // entries it wrote in stage 1 (i and i+256), so no pre-barrier
            // is needed for m==0; for m>0 the previous sync2 ordered writes.
            {
                const u64* xRrow = XY64 + (2 * m) * TILE_P * 32;
                const u64* xIrow = XY64 + (2 * m + 1) * TILE_P * 32;
                XSsm[tid]       = add2(xRrow[tid],       xIrow[tid]);
                XSsm[tid + 256] = add2(xRrow[tid + 256], xIrow[tid + 256]);
            }
            __syncthreads();   // W_m + XS_m visible; publishes X (m=0) / Y_{m-1}

            if (m < MODES - 1) {
#pragma unroll
                for (int k = 0; k < 12; k++)
                    wreg[k] = g_W2[(m + 1) * 3072 + tid + k * NTHR];
            }

            u64 aR[8], aI[8], aS[8];
            if (active) {
#pragma unroll
                for (int q = 0; q < 8; q++) { aR[q] = 0; aI[q] = 0; aS[q] = 0; }

                const u64* xR = XY64 + ((2 * m)     * TILE_P + pg) * 32;
                const u64* xI = XY64 + ((2 * m + 1) * TILE_P + pg) * 32;
                const u64* xS = XSsm + pg * 32;

#pragma unroll
                for (int c4 = 0; c4 < 16; c4++) {
                    ulonglong2 wr = WR2[(c4 << 6) + o];   // LDS.128, conflict-free
                    ulonglong2 wi = WI2[(c4 << 6) + o];
                    ulonglong2 ws = WS2[(c4 << 6) + o];
#pragma unroll
                    for (int q = 0; q < 8; q++) {
                        ulonglong2 xr = *reinterpret_cast<const ulonglong2*>(&xR[q * 32 + 2 * c4]);
                        ulonglong2 xi = *reinterpret_cast<const ulonglong2*>(&xI[q * 32 + 2 * c4]);
                        ulonglong2 xs = *reinterpret_cast<const ulonglong2*>(&xS[q * 32 + 2 * c4]);
                        fma2(aR[q], xr.x, wr.x); fma2(aR[q], xr.y, wr.y);
                        fma2(aI[q], xi.x, wi.x); fma2(aI[q], xi.y, wi.y);
                        fma2(aS[q], xs.x, ws.x); fma2(aS[q], xs.y, ws.y);
                    }
                }
            }

            __syncthreads();   // all reads of X_m / W_m / XS_m complete

            if (active) {
#pragma unroll
                for (int q = 0; q < 8; q++) {
                    float h1 = hadd(aR[q]);
                    float h2 = hadd(aI[q]);
                    float h3 = hadd(aS[q]);
                    float yr = h1 - h2;
                    float yi = h3 - h1 - h2;
                    XYf[((2 * m)     * TILE_P + pg + q) * 64 + o] = yr;
                    XYf[((2 * m + 1) * TILE_P + pg + q) * 64 + o] = yi;
                }
            }
        }
    }
    __syncthreads();   // Y complete

    // =============== Stage 3: truncated irfft from smem (folded) ===============
    {
        const int op = tid & 31;
        const int pp = tid >> 5;

        for (int pass = 0; pass < 2; pass++) {
            const int p = pp + pass * 8;

            float yRL[16], yRH[16], yIL[16], yIH[16];
#pragma unroll
            for (int m = 0; m < 16; m++) {
                unpack2(XY64[((2 * m)     * TILE_P + p) * 32 + op], yRL[m], yRH[m]);
                unpack2(XY64[((2 * m + 1) * TILE_P + p) * 32 + op], yIL[m], yIH[m]);
            }

            u64* outp = reinterpret_cast<u64*>(out) + (long)(p0 + p) * 32 + op;

            // t = 0
            {
                float c0 = 0.0f, c1 = 0.0f;
#pragma unroll
                for (int m = 0; m < 16; m++) {
                    const float g = alpha64(m);
                    c0 = fmaf(yRL[m], g, c0);
                    c1 = fmaf(yRH[m], g, c1);
                }
                outp[0] = pack2(c0, c1);
            }
            // t = 32
            {
                float c0 = 0.0f, c1 = 0.0f;
#pragma unroll
                for (int m = 0; m < 16; m++) {
                    const float g = (m & 1) ? -alpha64(m) : alpha64(m);
                    c0 = fmaf(yRL[m], g, c0);
                    c1 = fmaf(yRH[m], g, c1);
                }
                outp[32 * (SCOL / 2)] = pack2(c0, c1);
            }

#pragma unroll
            for (int t = 1; t < 32; t++) {
                float C0 = 0.0f, C1 = 0.0f, S0 = 0.0f, S1 = 0.0f;
#pragma unroll
                for (int m = 0; m < 16; m++) {
                    const float gc = alpha64(m) * cos64(m * t);
                    const float gs = alpha64(m) * cos64(m * t + 16);
                    if (gc != 0.0f) {
                        C0 = fmaf(yRL[m], gc, C0);
                        C1 = fmaf(yRH[m], gc, C1);
                    }
                    if (gs != 0.0f) {
                        S0 = fmaf(yIL[m], gs, S0);
                        S1 = fmaf(yIH[m], gs, S1);
                    }
                }
                outp[(long)t * (SCOL / 2)]        = pack2(C0 + S0, C1 + S1);
                outp[(long)(64 - t) * (SCOL / 2)] = pack2(C0 - S0, C1 - S1);
            }
        }
    }
}

// =====================================================================
extern "C" void kernel_launch(void* const* d_in, const int* in_sizes, int n_in,
                              void* d_out, int out_size) {
    const float* x = (const float*)d_in[0];   // [64][1024][16][64] f32
    const float* w = (const float*)d_in[1];   // [64][64][16][2] f32
    float* out     = (float*)d_out;           // [64][1024][16][64] f32
    (void)in_sizes; (void)n_in; (void)out_size;

    cudaFuncSetAttribute(fused_spectral, cudaFuncAttributeMaxDynamicSharedMemorySize, 184320);

    w_pack<<<192, 256>>>(w);
    fused_spectral<<<NBLK, NTHR, 184320>>>(x, out);
}

// round 12
// speedup vs baseline: 1.1161x; 1.1161x over previous
#include <cuda_runtime.h>

// Problem constants
#define TD     64
#define MODES  16
#define MRI    32          // 2*MODES
#define PD     16384       // N*D pixels
#define SCOL   1048576     // PD*64 floats per time row
#define TILE_P 16
#define NBLK   (PD / TILE_P)   // 1024 CTAs
#define NTHR   256
#define PXS    33          // u64 stride per pixel row (32 + 1 pad -> bank spread)

typedef unsigned long long u64;

// Packed, transposed weights: g_W[m][c2][o] = ( (WR[2c2],WR[2c2+1]), (WI[2c2],WI[2c2+1]) )
__device__ ulonglong2 g_W[MODES * 32 * 64];   // 512 KB

// ---------- compile-time DFT coefficients ----------
__host__ __device__ constexpr float cos64(int k) {
    constexpr float COSQ[17] = {
        1.0f,
        0.995184726672197f, 0.980785280403230f, 0.956940335732209f,
        0.923879532511287f, 0.881921264348355f, 0.831469612302545f,
        0.773010453362737f, 0.707106781186548f, 0.634393284163645f,
        0.555570233019602f, 0.471396736825998f, 0.382683432365090f,
        0.290284677254462f, 0.195090322016128f, 0.098017140329561f,
        0.0f
    };
    k &= 63;
    float s = 1.0f;
    if (k > 32) k = 64 - k;
    if (k > 16) { k = 32 - k; s = -1.0f; }
    return s * COSQ[k];
}
__host__ __device__ constexpr float alpha64(int m) {
    return ((m == 0) ? 1.0f : 2.0f) / 64.0f;
}

// ---------- packed f32x2 helpers ----------
__device__ __forceinline__ u64 pack2(float a, float b) {
    u64 r;
    asm("mov.b64 %0, {%1, %2};" : "=l"(r) : "f"(a), "f"(b));
    return r;
}
__device__ __forceinline__ void unpack2(u64 v, float &lo, float &hi) {
    asm("mov.b64 {%0, %1}, %2;" : "=f"(lo), "=f"(hi) : "l"(v));
}
__device__ __forceinline__ void fma2(u64 &d, u64 a, u64 b) {
    asm("fma.rn.f32x2 %0, %1, %2, %0;" : "+l"(d) : "l"(a), "l"(b));
}
__device__ __forceinline__ float hadd(u64 v) {
    float lo, hi;
    unpack2(v, lo, hi);
    return lo + hi;
}

// =====================================================================
// One-time weight repack: w[c][o][m][2]  ->  g_W[m][c2][o]
// =====================================================================
__global__ void __launch_bounds__(256) w_pack(const float* __restrict__ w) {
    int idx = blockIdx.x * 256 + threadIdx.x;     // 0 .. 32767
    int m  = idx >> 11;
    int c2 = (idx >> 6) & 31;
    int o  = idx & 63;
    int c0 = 2 * c2;
    const float* b0 = w + ((((c0    ) * 64 + o) * MODES + m) << 1);
    const float* b1 = w + ((((c0 + 1) * 64 + o) * MODES + m) << 1);
    ulonglong2 v;
    v.x = pack2(b0[0], b1[0]);
    v.y = pack2(b0[1], b1[1]);
    g_W[idx] = v;
}

// =====================================================================
// Fused spectral conv. 256 threads, 16 pixels per CTA, ~196 KB smem.
// smem layout (bytes):
//   [0      ,135168 ) XY  [mri][16p][33 u64] — px rows padded to 264B;
//                     X, overwritten in-place per mode by Y
//   [135168 ,167936 ) W buf 0  [c2][o] ulonglong2  (32 KB)
//   [167936 ,200704 ) W buf 1
// Stage 2 warp tile: 8px x 16o (lane = 1 px, 4 strided outputs).
// =====================================================================
__global__ void __launch_bounds__(NTHR, 1) fused_spectral(const float* __restrict__ x,
                                                          float* __restrict__ out) {
    extern __shared__ __align__(16) char smem[];
    u64*        XY64 = reinterpret_cast<u64*>(smem);
    float*      XYf  = reinterpret_cast<float*>(smem);
    ulonglong2* Wb0  = reinterpret_cast<ulonglong2*>(smem + 135168);
    ulonglong2* Wb1  = reinterpret_cast<ulonglong2*>(smem + 167936);

    const int tid = threadIdx.x;
    const int p0  = blockIdx.x * TILE_P;

    // ---- prefetch W for mode 0 (overlaps with stage 1 gmem reads) ----
    ulonglong2 wreg[8];
#pragma unroll
    for (int k = 0; k < 8; k++) wreg[k] = g_W[tid + k * NTHR];

    // =============== Stage 1: truncated rfft into smem (folded) ===============
    {
        const int cp = tid & 31;
        const int pp = tid >> 5;           // 0..7, warp-uniform

        for (int pass = 0; pass < 2; pass++) {
            const int p = pp + pass * 8;
            const u64* xp = reinterpret_cast<const u64*>(x) + (long)(p0 + p) * 32 + cp;

            float XcL[16], XcH[16], XsL[16], XsH[16];
            {
                float x0L, x0H, x32L, x32H;
                unpack2(xp[0], x0L, x0H);
                unpack2(xp[32 * (SCOL / 2)], x32L, x32H);
#pragma unroll
                for (int m = 0; m < 16; m++) {
                    if (m & 1) { XcL[m] = x0L - x32L; XcH[m] = x0H - x32H; }
                    else       { XcL[m] = x0L + x32L; XcH[m] = x0H + x32H; }
                    XsL[m] = 0.0f; XsH[m] = 0.0f;
                }
            }

#pragma unroll
            for (int t = 1; t < 32; t++) {
                float aL, aH, bL, bH;
                unpack2(xp[(long)t * (SCOL / 2)], aL, aH);
                unpack2(xp[(long)(64 - t) * (SCOL / 2)], bL, bH);
                const float eL = aL + bL, eH = aH + bH;
                const float oL = aL - bL, oH = aH - bH;
                XcL[0] += eL; XcH[0] += eH;
#pragma unroll
                for (int m = 1; m < 16; m++) {
                    const float fc = cos64(m * t);
                    const float fs = cos64(m * t + 16);
                    if (fc != 0.0f) {
                        XcL[m] = fmaf(eL, fc, XcL[m]);
                        XcH[m] = fmaf(eH, fc, XcH[m]);
                    }
                    if (fs != 0.0f) {
                        XsL[m] = fmaf(oL, fs, XsL[m]);
                        XsH[m] = fmaf(oH, fs, XsH[m]);
                    }
                }
            }

#pragma unroll
            for (int m = 0; m < 16; m++) {
                XY64[((2 * m)     * TILE_P + p) * PXS + cp] = pack2(XcL[m], XcH[m]);
                XY64[((2 * m + 1) * TILE_P + p) * PXS + cp] = pack2(XsL[m], XsH[m]);
            }
        }
        // published at the first syncthreads inside the mode loop
    }

    // =============== Stage 2: per-mode complex channel mix ===============
    // Warp tile 8px x 16o. lane = pxi(8) x osub(4); lane's outputs o = og*16
    // + osub + 4j (strided so each W LDS.128's 4 distinct addrs are 64B-contig).
    {
        const int lane  = tid & 31;
        const int wrp   = tid >> 5;
        const int og    = wrp & 3;
        const int pxg   = wrp >> 2;               // 0 or 1
        const int pxi   = lane & 7;
        const int osub  = lane >> 3;              // 0..3
        const int px    = pxg * 8 + pxi;
        const int obase = og * 16 + osub;         // o = obase + 4j

        for (int m = 0; m < MODES; m++) {
            ulonglong2* Wc = (m & 1) ? Wb1 : Wb0;
#pragma unroll
            for (int k = 0; k < 8; k++) Wc[tid + k * NTHR] = wreg[k];
            __syncthreads();   // W_m visible; publishes X (m=0) / Y_{m-1}

            if (m < MODES - 1) {
#pragma unroll
                for (int k = 0; k < 8; k++)
                    wreg[k] = g_W[(m + 1) * 2048 + tid + k * NTHR];
            }

            const u64* xRrow = XY64 + ((2 * m)     * TILE_P + px) * PXS;
            const u64* xIrow = XY64 + ((2 * m + 1) * TILE_P + px) * PXS;

            // P = sum xr*wr, Q = sum xi*wi, T = sum (xr*wi + xi*wr)
            u64 P[4], Q[4], T[4];
#pragma unroll
            for (int j = 0; j < 4; j++) { P[j] = 0; Q[j] = 0; T[j] = 0; }

#pragma unroll 8
            for (int c2 = 0; c2 < 32; c2++) {
                u64 xr = xRrow[c2];                // LDS.64, 8 distinct, 1 wf
                u64 xi = xIrow[c2];
#pragma unroll
                for (int j = 0; j < 4; j++) {
                    ulonglong2 wv = Wc[(c2 << 6) + obase + 4 * j];  // LDS.128, 1 wf
                    fma2(P[j], xr, wv.x);
                    fma2(Q[j], xi, wv.y);
                    fma2(T[j], xr, wv.y);
                    fma2(T[j], xi, wv.x);
                }
            }

            __syncthreads();   // all reads of X_m / W_m complete before overwrite

#pragma unroll
            for (int j = 0; j < 4; j++) {
                const int o = obase + 4 * j;
                float yr = hadd(P[j]) - hadd(Q[j]);
                float yi = hadd(T[j]);
                XYf[(((2 * m)     * TILE_P + px) * PXS) * 2 + o] = yr;
                XYf[(((2 * m + 1) * TILE_P + px) * PXS) * 2 + o] = yi;
            }
        }
    }
    __syncthreads();   // Y complete

    // =============== Stage 3: truncated irfft from smem (folded) ===============
    {
        const int op = tid & 31;
        const int pp = tid >> 5;

        for (int pass = 0; pass < 2; pass++) {
            const int p = pp + pass * 8;

            float yRL[16], yRH[16], yIL[16], yIH[16];
#pragma unroll
            for (int m = 0; m < 16; m++) {
                unpack2(XY64[((2 * m)     * TILE_P + p) * PXS + op], yRL[m], yRH[m]);
                unpack2(XY64[((2 * m + 1) * TILE_P + p) * PXS + op], yIL[m], yIH[m]);
            }

            u64* outp = reinterpret_cast<u64*>(out) + (long)(p0 + p) * 32 + op;

            // t = 0
            {
                float c0 = 0.0f, c1 = 0.0f;
#pragma unroll
                for (int m = 0; m < 16; m++) {
                    const float g = alpha64(m);
                    c0 = fmaf(yRL[m], g, c0);
                    c1 = fmaf(yRH[m], g, c1);
                }
                outp[0] = pack2(c0, c1);
            }
            // t = 32
            {
                float c0 = 0.0f, c1 = 0.0f;
#pragma unroll
                for (int m = 0; m < 16; m++) {
                    const float g = (m & 1) ? -alpha64(m) : alpha64(m);
                    c0 = fmaf(yRL[m], g, c0);
                    c1 = fmaf(yRH[m], g, c1);
                }
                outp[32 * (SCOL / 2)] = pack2(c0, c1);
            }

#pragma unroll
            for (int t = 1; t < 32; t++) {
                float C0 = 0.0f, C1 = 0.0f, S0 = 0.0f, S1 = 0.0f;
#pragma unroll
                for (int m = 0; m < 16; m++) {
                    const float gc = alpha64(m) * cos64(m * t);
                    const float gs = alpha64(m) * cos64(m * t + 16);
                    if (gc != 0.0f) {
                        C0 = fmaf(yRL[m], gc, C0);
                        C1 = fmaf(yRH[m], gc, C1);
                    }
                    if (gs != 0.0f) {
                        S0 = fmaf(yIL[m], gs, S0);
                        S1 = fmaf(yIH[m], gs, S1);
                    }
                }
                outp[(long)t * (SCOL / 2)]        = pack2(C0 + S0, C1 + S1);
                outp[(long)(64 - t) * (SCOL / 2)] = pack2(C0 - S0, C1 - S1);
            }
        }
    }
}

// =====================================================================
extern "C" void kernel_launch(void* const* d_in, const int* in_sizes, int n_in,
                              void* d_out, int out_size) {
    const float* x = (const float*)d_in[0];   // [64][1024][16][64] f32
    const float* w = (const float*)d_in[1];   // [64][64][16][2] f32
    float* out     = (float*)d_out;           // [64][1024][16][64] f32
    (void)in_sizes; (void)n_in; (void)out_size;

    cudaFuncSetAttribute(fused_spectral, cudaFuncAttributeMaxDynamicSharedMemorySize, 200704);

    w_pack<<<128, 256>>>(w);
    fused_spectral<<<NBLK, NTHR, 200704>>>(x, out);
}